// round 7
// baseline (speedup 1.0000x reference)
#include <cuda_runtime.h>
#include <cstdint>

// FlashAttention via 3xTF32 mma.sync, 8 warps = 2 row-groups x 4 key-quarters.
// Warp tile M=32 (2 m-frags) amortizes B-fragment smem bytes over 2x work.
// P is warp-private (computed and consumed by the same warp).
// N=8192, D=128, no softmax scaling. sm_103a.

#define NSEQ 8192
#define DIM 128
#define BM 64
#define BN 64
#define SQK 132   // 132 % 32 == 4 -> (4g+tig) banks conflict-free
#define SVS 136   // 136 % 32 == 8 -> (8tig+g) banks conflict-free
#define SPS 68    //  68 % 32 == 4

// SQ + SKh + SKl (64x132 each) + SVh + SVl (64x136) + SP (64x68) + stats
#define SMEM_FLOATS (3*BM*SQK + 2*BN*SVS + BM*SPS + 512)

__device__ __forceinline__ uint32_t f2tf(float x) {
    uint32_t r;
    asm("cvt.rna.tf32.f32 %0, %1;" : "=r"(r) : "f"(x));
    return r;
}
__device__ __forceinline__ void tf_split(float x, uint32_t& hi, uint32_t& lo) {
    hi = f2tf(x);
    lo = f2tf(x - __uint_as_float(hi));
}
__device__ __forceinline__ void split1(float x, float& h, float& l) {
    h = __uint_as_float(f2tf(x));
    l = __uint_as_float(f2tf(x - h));
}
__device__ __forceinline__ void mma_tf32(float* c, const uint32_t* a,
                                         uint32_t b0, uint32_t b1) {
    asm volatile(
        "mma.sync.aligned.m16n8k8.row.col.f32.tf32.tf32.f32 "
        "{%0,%1,%2,%3}, {%4,%5,%6,%7}, {%8,%9}, {%0,%1,%2,%3};"
        : "+f"(c[0]), "+f"(c[1]), "+f"(c[2]), "+f"(c[3])
        : "r"(a[0]), "r"(a[1]), "r"(a[2]), "r"(a[3]), "r"(b0), "r"(b1));
}

__global__ __launch_bounds__(256, 1)
void fa_tf32_kernel(const float* __restrict__ q,
                    const float* __restrict__ k,
                    const float* __restrict__ v,
                    float* __restrict__ out) {
    extern __shared__ float sm[];
    float* SQ  = sm;                      // 64 x 132 fp32
    float* SKh = SQ  + BM * SQK;          // 64 x 132 tf32-hi
    float* SKl = SKh + BN * SQK;          // 64 x 132 tf32-lo
    float* SVh = SKl + BN * SQK;          // 64 x 136
    float* SVl = SVh + BN * SVS;          // 64 x 136
    float* SP  = SVl + BN * SVS;          // 64 x 68 fp32 (warp-private quarters)
    float* SMx = SP  + BM * SPS;          // 4 x 64
    float* SSm = SMx + 256;               // 4 x 64

    const int tid  = threadIdx.x;
    const int warp = tid >> 5;
    const int lane = tid & 31;
    const int g    = lane >> 2;
    const int tig  = lane & 3;
    const int rg   = warp & 1;     // row group: rows rg*32 .. +31
    const int h    = warp >> 1;    // key/j quarter: h*16 .. +15
    const int wr   = rg * 32;
    const int qrow0 = blockIdx.x * BM;

    // ---- load Q tile fp32 ----
    {
        const float4* qg = (const float4*)(q + (size_t)qrow0 * DIM);
        #pragma unroll
        for (int t = 0; t < 8; t++) {
            int i = tid + 256 * t;       // 2048 float4
            int row = i >> 5;
            int dd = (i & 31) << 2;
            *(float4*)(SQ + row * SQK + dd) = qg[i];
        }
    }

    float o[2][16][4];
    #pragma unroll
    for (int mf = 0; mf < 2; mf++)
        #pragma unroll
        for (int nt = 0; nt < 16; nt++)
            #pragma unroll
            for (int i = 0; i < 4; i++) o[mf][nt][i] = 0.0f;

    float mm[2][2], ll[2][2];
    #pragma unroll
    for (int mf = 0; mf < 2; mf++) {
        mm[mf][0] = -1e30f; mm[mf][1] = -1e30f;
        ll[mf][0] = 0.0f;   ll[mf][1] = 0.0f;
    }

    #pragma unroll 1
    for (int kb = 0; kb < NSEQ / BN; kb++) {
        __syncthreads();   // prior iter's SK/SV reads complete

        // ---- stream K,V; split hi/lo in registers ----
        {
            const float4* kg = (const float4*)(k + (size_t)kb * BN * DIM);
            const float4* vg = (const float4*)(v + (size_t)kb * BN * DIM);
            #pragma unroll
            for (int t = 0; t < 8; t++) {
                int i = tid + 256 * t;
                int row = i >> 5;
                int dd = (i & 31) << 2;
                float4 kx = kg[i], vx = vg[i];
                float4 xh, xl;
                split1(kx.x, xh.x, xl.x); split1(kx.y, xh.y, xl.y);
                split1(kx.z, xh.z, xl.z); split1(kx.w, xh.w, xl.w);
                *(float4*)(SKh + row * SQK + dd) = xh;
                *(float4*)(SKl + row * SQK + dd) = xl;
                split1(vx.x, xh.x, xl.x); split1(vx.y, xh.y, xl.y);
                split1(vx.z, xh.z, xl.z); split1(vx.w, xh.w, xl.w);
                *(float4*)(SVh + row * SVS + dd) = xh;
                *(float4*)(SVl + row * SVS + dd) = xl;
            }
        }
        __syncthreads();

        // ---- S = Q K^T : 2 m-frags x 2 n-tiles (this warp's 16 keys) ----
        float s[2][2][4];
        #pragma unroll
        for (int mf = 0; mf < 2; mf++)
            #pragma unroll
            for (int nt = 0; nt < 2; nt++)
                #pragma unroll
                for (int i = 0; i < 4; i++) s[mf][nt][i] = 0.0f;

        #pragma unroll 4
        for (int kc = 0; kc < DIM / 8; kc++) {
            uint32_t ah[2][4], al[2][4];
            #pragma unroll
            for (int mf = 0; mf < 2; mf++) {
                const float* Sq = SQ + (wr + 16 * mf + g) * SQK + 8 * kc + tig;
                tf_split(Sq[0],           ah[mf][0], al[mf][0]);
                tf_split(Sq[8 * SQK],     ah[mf][1], al[mf][1]);
                tf_split(Sq[4],           ah[mf][2], al[mf][2]);
                tf_split(Sq[8 * SQK + 4], ah[mf][3], al[mf][3]);
            }
            #pragma unroll
            for (int nt = 0; nt < 2; nt++) {
                int ntg = h * 2 + nt;
                const float* kph = SKh + (ntg * 8 + g) * SQK + 8 * kc + tig;
                const float* kpl = SKl + (ntg * 8 + g) * SQK + 8 * kc + tig;
                uint32_t bh0 = __float_as_uint(kph[0]);
                uint32_t bh1 = __float_as_uint(kph[4]);
                uint32_t bl0 = __float_as_uint(kpl[0]);
                uint32_t bl1 = __float_as_uint(kpl[4]);
                #pragma unroll
                for (int mf = 0; mf < 2; mf++) {
                    mma_tf32(s[mf][nt], ah[mf], bh0, bh1);
                    mma_tf32(s[mf][nt], ah[mf], bl0, bl1);
                    mma_tf32(s[mf][nt], al[mf], bh0, bh1);
                }
            }
        }

        // ---- softmax: local row max, 4-way cross-quarter exchange ----
        float mx[2][2];
        #pragma unroll
        for (int mf = 0; mf < 2; mf++) {
            mx[mf][0] = fmaxf(fmaxf(s[mf][0][0], s[mf][0][1]),
                              fmaxf(s[mf][1][0], s[mf][1][1]));
            mx[mf][1] = fmaxf(fmaxf(s[mf][0][2], s[mf][0][3]),
                              fmaxf(s[mf][1][2], s[mf][1][3]));
            #pragma unroll
            for (int w = 1; w < 4; w <<= 1) {
                mx[mf][0] = fmaxf(mx[mf][0], __shfl_xor_sync(0xffffffffu, mx[mf][0], w));
                mx[mf][1] = fmaxf(mx[mf][1], __shfl_xor_sync(0xffffffffu, mx[mf][1], w));
            }
        }
        if (tig == 0) {
            #pragma unroll
            for (int mf = 0; mf < 2; mf++) {
                SMx[h * 64 + wr + 16 * mf + g]     = mx[mf][0];
                SMx[h * 64 + wr + 16 * mf + 8 + g] = mx[mf][1];
            }
        }
        __syncthreads();

        float alpha[2][2], sum[2][2];
        #pragma unroll
        for (int mf = 0; mf < 2; mf++) {
            #pragma unroll
            for (int grp = 0; grp < 2; grp++) {
                int rl = wr + 16 * mf + 8 * grp + g;
                float gm = fmaxf(fmaxf(SMx[rl], SMx[64 + rl]),
                                 fmaxf(SMx[128 + rl], SMx[192 + rl]));
                float mn = fmaxf(mm[mf][grp], gm);
                alpha[mf][grp] = __expf(mm[mf][grp] - mn);
                mm[mf][grp] = mn;
                sum[mf][grp] = 0.0f;
            }
            #pragma unroll
            for (int nt = 0; nt < 2; nt++) {
                s[mf][nt][0] = __expf(s[mf][nt][0] - mm[mf][0]);
                s[mf][nt][1] = __expf(s[mf][nt][1] - mm[mf][0]);
                s[mf][nt][2] = __expf(s[mf][nt][2] - mm[mf][1]);
                s[mf][nt][3] = __expf(s[mf][nt][3] - mm[mf][1]);
                sum[mf][0] += s[mf][nt][0] + s[mf][nt][1];
                sum[mf][1] += s[mf][nt][2] + s[mf][nt][3];
            }
            #pragma unroll
            for (int w = 1; w < 4; w <<= 1) {
                sum[mf][0] += __shfl_xor_sync(0xffffffffu, sum[mf][0], w);
                sum[mf][1] += __shfl_xor_sync(0xffffffffu, sum[mf][1], w);
            }
        }
        if (tig == 0) {
            #pragma unroll
            for (int mf = 0; mf < 2; mf++) {
                SSm[h * 64 + wr + 16 * mf + g]     = sum[mf][0];
                SSm[h * 64 + wr + 16 * mf + 8 + g] = sum[mf][1];
            }
        }
        // write P (warp-private quarter: rows of rg, cols of h)
        #pragma unroll
        for (int mf = 0; mf < 2; mf++)
            #pragma unroll
            for (int nt = 0; nt < 2; nt++) {
                int col = h * 16 + 8 * nt + 2 * tig;
                *(float2*)(SP + (wr + 16 * mf + g) * SPS + col) =
                    make_float2(s[mf][nt][0], s[mf][nt][1]);
                *(float2*)(SP + (wr + 16 * mf + 8 + g) * SPS + col) =
                    make_float2(s[mf][nt][2], s[mf][nt][3]);
            }
        __syncthreads();

        #pragma unroll
        for (int mf = 0; mf < 2; mf++)
            #pragma unroll
            for (int grp = 0; grp < 2; grp++) {
                int rl = wr + 16 * mf + 8 * grp + g;
                float tot = (SSm[rl] + SSm[64 + rl]) + (SSm[128 + rl] + SSm[192 + rl]);
                ll[mf][grp] = ll[mf][grp] * alpha[mf][grp] + tot;
            }

        // rescale O
        #pragma unroll
        for (int mf = 0; mf < 2; mf++)
            #pragma unroll
            for (int nt = 0; nt < 16; nt++) {
                o[mf][nt][0] *= alpha[mf][0]; o[mf][nt][1] *= alpha[mf][0];
                o[mf][nt][2] *= alpha[mf][1]; o[mf][nt][3] *= alpha[mf][1];
            }

        // ---- O += P V over this warp's j-quarter (16 j's = 2 k-chunks) ----
        #pragma unroll
        for (int kcl = 0; kcl < 2; kcl++) {
            int kcg = h * 2 + kcl;
            uint32_t pah[2][4], pal[2][4];
            #pragma unroll
            for (int mf = 0; mf < 2; mf++) {
                const float* Sp = SP + (wr + 16 * mf + g) * SPS + 8 * kcg + tig;
                tf_split(Sp[0],           pah[mf][0], pal[mf][0]);
                tf_split(Sp[8 * SPS],     pah[mf][1], pal[mf][1]);
                tf_split(Sp[4],           pah[mf][2], pal[mf][2]);
                tf_split(Sp[8 * SPS + 4], pah[mf][3], pal[mf][3]);
            }
            #pragma unroll
            for (int nt = 0; nt < 16; nt++) {
                const float* vph = SVh + (8 * kcg + tig) * SVS + 8 * nt + g;
                const float* vpl = SVl + (8 * kcg + tig) * SVS + 8 * nt + g;
                uint32_t bh0 = __float_as_uint(vph[0]);
                uint32_t bh1 = __float_as_uint(vph[4 * SVS]);
                uint32_t bl0 = __float_as_uint(vpl[0]);
                uint32_t bl1 = __float_as_uint(vpl[4 * SVS]);
                #pragma unroll
                for (int mf = 0; mf < 2; mf++) {
                    mma_tf32(o[mf][nt], pah[mf], bh0, bh1);
                    mma_tf32(o[mf][nt], pah[mf], bl0, bl1);
                    mma_tf32(o[mf][nt], pal[mf], bh0, bh1);
                }
            }
        }
    }

    // ---- epilogue: 4-way quarter combine via smem, normalize, store ----
    __syncthreads();
    if (h != 0) {
        float* OB = (h == 1) ? SQ : (h == 2) ? SKh : SKl;
        #pragma unroll
        for (int mf = 0; mf < 2; mf++)
            #pragma unroll
            for (int nt = 0; nt < 16; nt++) {
                int col = 8 * nt + 2 * tig;
                *(float2*)(OB + (wr + 16 * mf + g) * SQK + col) =
                    make_float2(o[mf][nt][0], o[mf][nt][1]);
                *(float2*)(OB + (wr + 16 * mf + 8 + g) * SQK + col) =
                    make_float2(o[mf][nt][2], o[mf][nt][3]);
            }
    }
    __syncthreads();
    if (h == 0) {
        #pragma unroll
        for (int mf = 0; mf < 2; mf++) {
            float i0 = 1.0f / ll[mf][0];
            float i1 = 1.0f / ll[mf][1];
            int ra = wr + 16 * mf + g;
            int rb = ra + 8;
            #pragma unroll
            for (int nt = 0; nt < 16; nt++) {
                int col = 8 * nt + 2 * tig;
                float2 a0 = *(float2*)(SQ  + ra * SQK + col);
                float2 b0 = *(float2*)(SKh + ra * SQK + col);
                float2 c0 = *(float2*)(SKl + ra * SQK + col);
                float2 a1 = *(float2*)(SQ  + rb * SQK + col);
                float2 b1 = *(float2*)(SKh + rb * SQK + col);
                float2 c1 = *(float2*)(SKl + rb * SQK + col);
                *(float2*)(out + (size_t)(qrow0 + ra) * DIM + col) =
                    make_float2((o[mf][nt][0] + a0.x + b0.x + c0.x) * i0,
                                (o[mf][nt][1] + a0.y + b0.y + c0.y) * i0);
                *(float2*)(out + (size_t)(qrow0 + rb) * DIM + col) =
                    make_float2((o[mf][nt][2] + a1.x + b1.x + c1.x) * i1,
                                (o[mf][nt][3] + a1.y + b1.y + c1.y) * i1);
            }
        }
    }
}

extern "C" void kernel_launch(void* const* d_in, const int* in_sizes, int n_in,
                              void* d_out, int out_size) {
    const float* q = (const float*)d_in[0];
    const float* k = (const float*)d_in[1];
    const float* v = (const float*)d_in[2];
    float* out = (float*)d_out;

    const int smem_bytes = SMEM_FLOATS * (int)sizeof(float);  // 190,464 B
    cudaFuncSetAttribute(fa_tf32_kernel,
                         cudaFuncAttributeMaxDynamicSharedMemorySize, smem_bytes);

    dim3 grid(NSEQ / BM);   // 128 CTAs
    dim3 block(256);
    fa_tf32_kernel<<<grid, block, smem_bytes>>>(q, k, v, out);
}

// round 8
// speedup vs baseline: 1.0004x; 1.0004x over previous
#include <cuda_runtime.h>
#include <cstdint>

// FlashAttention via 3xTF32 mma.sync, 8 warps = 2 row-groups x 4 key-quarters.
// Warp tile M=32 (2 m-frags) amortizes B-fragment smem bytes over 2x work.
// P is warp-private (computed and consumed by the same warp).
// N=8192, D=128, no softmax scaling. sm_103a.

#define NSEQ 8192
#define DIM 128
#define BM 64
#define BN 64
#define SQK 132   // 132 % 32 == 4 -> (4g+tig) banks conflict-free
#define SVS 136   // 136 % 32 == 8 -> (8tig+g) banks conflict-free
#define SPS 68    //  68 % 32 == 4

// SQ + SKh + SKl (64x132 each) + SVh + SVl (64x136) + SP (64x68) + stats
#define SMEM_FLOATS (3*BM*SQK + 2*BN*SVS + BM*SPS + 512)

__device__ __forceinline__ uint32_t f2tf(float x) {
    uint32_t r;
    asm("cvt.rna.tf32.f32 %0, %1;" : "=r"(r) : "f"(x));
    return r;
}
__device__ __forceinline__ void tf_split(float x, uint32_t& hi, uint32_t& lo) {
    hi = f2tf(x);
    lo = f2tf(x - __uint_as_float(hi));
}
__device__ __forceinline__ void split1(float x, float& h, float& l) {
    h = __uint_as_float(f2tf(x));
    l = __uint_as_float(f2tf(x - h));
}
__device__ __forceinline__ void mma_tf32(float* c, const uint32_t* a,
                                         uint32_t b0, uint32_t b1) {
    asm volatile(
        "mma.sync.aligned.m16n8k8.row.col.f32.tf32.tf32.f32 "
        "{%0,%1,%2,%3}, {%4,%5,%6,%7}, {%8,%9}, {%0,%1,%2,%3};"
        : "+f"(c[0]), "+f"(c[1]), "+f"(c[2]), "+f"(c[3])
        : "r"(a[0]), "r"(a[1]), "r"(a[2]), "r"(a[3]), "r"(b0), "r"(b1));
}

__global__ __launch_bounds__(256, 1)
void fa_tf32_kernel(const float* __restrict__ q,
                    const float* __restrict__ k,
                    const float* __restrict__ v,
                    float* __restrict__ out) {
    extern __shared__ float sm[];
    float* SQ  = sm;                      // 64 x 132 fp32
    float* SKh = SQ  + BM * SQK;          // 64 x 132 tf32-hi
    float* SKl = SKh + BN * SQK;          // 64 x 132 tf32-lo
    float* SVh = SKl + BN * SQK;          // 64 x 136
    float* SVl = SVh + BN * SVS;          // 64 x 136
    float* SP  = SVl + BN * SVS;          // 64 x 68 fp32 (warp-private quarters)
    float* SMx = SP  + BM * SPS;          // 4 x 64
    float* SSm = SMx + 256;               // 4 x 64

    const int tid  = threadIdx.x;
    const int warp = tid >> 5;
    const int lane = tid & 31;
    const int g    = lane >> 2;
    const int tig  = lane & 3;
    const int rg   = warp & 1;     // row group: rows rg*32 .. +31
    const int h    = warp >> 1;    // key/j quarter: h*16 .. +15
    const int wr   = rg * 32;
    const int qrow0 = blockIdx.x * BM;

    // ---- load Q tile fp32 ----
    {
        const float4* qg = (const float4*)(q + (size_t)qrow0 * DIM);
        #pragma unroll
        for (int t = 0; t < 8; t++) {
            int i = tid + 256 * t;       // 2048 float4
            int row = i >> 5;
            int dd = (i & 31) << 2;
            *(float4*)(SQ + row * SQK + dd) = qg[i];
        }
    }

    float o[2][16][4];
    #pragma unroll
    for (int mf = 0; mf < 2; mf++)
        #pragma unroll
        for (int nt = 0; nt < 16; nt++)
            #pragma unroll
            for (int i = 0; i < 4; i++) o[mf][nt][i] = 0.0f;

    float mm[2][2], ll[2][2];
    #pragma unroll
    for (int mf = 0; mf < 2; mf++) {
        mm[mf][0] = -1e30f; mm[mf][1] = -1e30f;
        ll[mf][0] = 0.0f;   ll[mf][1] = 0.0f;
    }

    #pragma unroll 1
    for (int kb = 0; kb < NSEQ / BN; kb++) {
        __syncthreads();   // prior iter's SK/SV reads complete

        // ---- stream K,V; split hi/lo in registers ----
        {
            const float4* kg = (const float4*)(k + (size_t)kb * BN * DIM);
            const float4* vg = (const float4*)(v + (size_t)kb * BN * DIM);
            #pragma unroll
            for (int t = 0; t < 8; t++) {
                int i = tid + 256 * t;
                int row = i >> 5;
                int dd = (i & 31) << 2;
                float4 kx = kg[i], vx = vg[i];
                float4 xh, xl;
                split1(kx.x, xh.x, xl.x); split1(kx.y, xh.y, xl.y);
                split1(kx.z, xh.z, xl.z); split1(kx.w, xh.w, xl.w);
                *(float4*)(SKh + row * SQK + dd) = xh;
                *(float4*)(SKl + row * SQK + dd) = xl;
                split1(vx.x, xh.x, xl.x); split1(vx.y, xh.y, xl.y);
                split1(vx.z, xh.z, xl.z); split1(vx.w, xh.w, xl.w);
                *(float4*)(SVh + row * SVS + dd) = xh;
                *(float4*)(SVl + row * SVS + dd) = xl;
            }
        }
        __syncthreads();

        // ---- S = Q K^T : 2 m-frags x 2 n-tiles (this warp's 16 keys) ----
        float s[2][2][4];
        #pragma unroll
        for (int mf = 0; mf < 2; mf++)
            #pragma unroll
            for (int nt = 0; nt < 2; nt++)
                #pragma unroll
                for (int i = 0; i < 4; i++) s[mf][nt][i] = 0.0f;

        #pragma unroll 4
        for (int kc = 0; kc < DIM / 8; kc++) {
            uint32_t ah[2][4], al[2][4];
            #pragma unroll
            for (int mf = 0; mf < 2; mf++) {
                const float* Sq = SQ + (wr + 16 * mf + g) * SQK + 8 * kc + tig;
                tf_split(Sq[0],           ah[mf][0], al[mf][0]);
                tf_split(Sq[8 * SQK],     ah[mf][1], al[mf][1]);
                tf_split(Sq[4],           ah[mf][2], al[mf][2]);
                tf_split(Sq[8 * SQK + 4], ah[mf][3], al[mf][3]);
            }
            #pragma unroll
            for (int nt = 0; nt < 2; nt++) {
                int ntg = h * 2 + nt;
                const float* kph = SKh + (ntg * 8 + g) * SQK + 8 * kc + tig;
                const float* kpl = SKl + (ntg * 8 + g) * SQK + 8 * kc + tig;
                uint32_t bh0 = __float_as_uint(kph[0]);
                uint32_t bh1 = __float_as_uint(kph[4]);
                uint32_t bl0 = __float_as_uint(kpl[0]);
                uint32_t bl1 = __float_as_uint(kpl[4]);
                #pragma unroll
                for (int mf = 0; mf < 2; mf++) {
                    mma_tf32(s[mf][nt], ah[mf], bh0, bh1);
                    mma_tf32(s[mf][nt], ah[mf], bl0, bl1);
                    mma_tf32(s[mf][nt], al[mf], bh0, bh1);
                }
            }
        }

        // ---- softmax: local row max, 4-way cross-quarter exchange ----
        float mx[2][2];
        #pragma unroll
        for (int mf = 0; mf < 2; mf++) {
            mx[mf][0] = fmaxf(fmaxf(s[mf][0][0], s[mf][0][1]),
                              fmaxf(s[mf][1][0], s[mf][1][1]));
            mx[mf][1] = fmaxf(fmaxf(s[mf][0][2], s[mf][0][3]),
                              fmaxf(s[mf][1][2], s[mf][1][3]));
            #pragma unroll
            for (int w = 1; w < 4; w <<= 1) {
                mx[mf][0] = fmaxf(mx[mf][0], __shfl_xor_sync(0xffffffffu, mx[mf][0], w));
                mx[mf][1] = fmaxf(mx[mf][1], __shfl_xor_sync(0xffffffffu, mx[mf][1], w));
            }
        }
        if (tig == 0) {
            #pragma unroll
            for (int mf = 0; mf < 2; mf++) {
                SMx[h * 64 + wr + 16 * mf + g]     = mx[mf][0];
                SMx[h * 64 + wr + 16 * mf + 8 + g] = mx[mf][1];
            }
        }
        __syncthreads();

        float alpha[2][2], sum[2][2];
        #pragma unroll
        for (int mf = 0; mf < 2; mf++) {
            #pragma unroll
            for (int grp = 0; grp < 2; grp++) {
                int rl = wr + 16 * mf + 8 * grp + g;
                float gm = fmaxf(fmaxf(SMx[rl], SMx[64 + rl]),
                                 fmaxf(SMx[128 + rl], SMx[192 + rl]));
                float mn = fmaxf(mm[mf][grp], gm);
                alpha[mf][grp] = __expf(mm[mf][grp] - mn);
                mm[mf][grp] = mn;
                sum[mf][grp] = 0.0f;
            }
            #pragma unroll
            for (int nt = 0; nt < 2; nt++) {
                s[mf][nt][0] = __expf(s[mf][nt][0] - mm[mf][0]);
                s[mf][nt][1] = __expf(s[mf][nt][1] - mm[mf][0]);
                s[mf][nt][2] = __expf(s[mf][nt][2] - mm[mf][1]);
                s[mf][nt][3] = __expf(s[mf][nt][3] - mm[mf][1]);
                sum[mf][0] += s[mf][nt][0] + s[mf][nt][1];
                sum[mf][1] += s[mf][nt][2] + s[mf][nt][3];
            }
            #pragma unroll
            for (int w = 1; w < 4; w <<= 1) {
                sum[mf][0] += __shfl_xor_sync(0xffffffffu, sum[mf][0], w);
                sum[mf][1] += __shfl_xor_sync(0xffffffffu, sum[mf][1], w);
            }
        }
        if (tig == 0) {
            #pragma unroll
            for (int mf = 0; mf < 2; mf++) {
                SSm[h * 64 + wr + 16 * mf + g]     = sum[mf][0];
                SSm[h * 64 + wr + 16 * mf + 8 + g] = sum[mf][1];
            }
        }
        // write P (warp-private quarter: rows of rg, cols of h)
        #pragma unroll
        for (int mf = 0; mf < 2; mf++)
            #pragma unroll
            for (int nt = 0; nt < 2; nt++) {
                int col = h * 16 + 8 * nt + 2 * tig;
                *(float2*)(SP + (wr + 16 * mf + g) * SPS + col) =
                    make_float2(s[mf][nt][0], s[mf][nt][1]);
                *(float2*)(SP + (wr + 16 * mf + 8 + g) * SPS + col) =
                    make_float2(s[mf][nt][2], s[mf][nt][3]);
            }
        __syncthreads();

        #pragma unroll
        for (int mf = 0; mf < 2; mf++)
            #pragma unroll
            for (int grp = 0; grp < 2; grp++) {
                int rl = wr + 16 * mf + 8 * grp + g;
                float tot = (SSm[rl] + SSm[64 + rl]) + (SSm[128 + rl] + SSm[192 + rl]);
                ll[mf][grp] = ll[mf][grp] * alpha[mf][grp] + tot;
            }

        // rescale O
        #pragma unroll
        for (int mf = 0; mf < 2; mf++)
            #pragma unroll
            for (int nt = 0; nt < 16; nt++) {
                o[mf][nt][0] *= alpha[mf][0]; o[mf][nt][1] *= alpha[mf][0];
                o[mf][nt][2] *= alpha[mf][1]; o[mf][nt][3] *= alpha[mf][1];
            }

        // ---- O += P V over this warp's j-quarter (16 j's = 2 k-chunks) ----
        #pragma unroll
        for (int kcl = 0; kcl < 2; kcl++) {
            int kcg = h * 2 + kcl;
            uint32_t pah[2][4], pal[2][4];
            #pragma unroll
            for (int mf = 0; mf < 2; mf++) {
                const float* Sp = SP + (wr + 16 * mf + g) * SPS + 8 * kcg + tig;
                tf_split(Sp[0],           pah[mf][0], pal[mf][0]);
                tf_split(Sp[8 * SPS],     pah[mf][1], pal[mf][1]);
                tf_split(Sp[4],           pah[mf][2], pal[mf][2]);
                tf_split(Sp[8 * SPS + 4], pah[mf][3], pal[mf][3]);
            }
            #pragma unroll
            for (int nt = 0; nt < 16; nt++) {
                const float* vph = SVh + (8 * kcg + tig) * SVS + 8 * nt + g;
                const float* vpl = SVl + (8 * kcg + tig) * SVS + 8 * nt + g;
                uint32_t bh0 = __float_as_uint(vph[0]);
                uint32_t bh1 = __float_as_uint(vph[4 * SVS]);
                uint32_t bl0 = __float_as_uint(vpl[0]);
                uint32_t bl1 = __float_as_uint(vpl[4 * SVS]);
                #pragma unroll
                for (int mf = 0; mf < 2; mf++) {
                    mma_tf32(o[mf][nt], pah[mf], bh0, bh1);
                    mma_tf32(o[mf][nt], pah[mf], bl0, bl1);
                    mma_tf32(o[mf][nt], pal[mf], bh0, bh1);
                }
            }
        }
    }

    // ---- epilogue: 4-way quarter combine via smem, normalize, store ----
    __syncthreads();
    if (h != 0) {
        float* OB = (h == 1) ? SQ : (h == 2) ? SKh : SKl;
        #pragma unroll
        for (int mf = 0; mf < 2; mf++)
            #pragma unroll
            for (int nt = 0; nt < 16; nt++) {
                int col = 8 * nt + 2 * tig;
                *(float2*)(OB + (wr + 16 * mf + g) * SQK + col) =
                    make_float2(o[mf][nt][0], o[mf][nt][1]);
                *(float2*)(OB + (wr + 16 * mf + 8 + g) * SQK + col) =
                    make_float2(o[mf][nt][2], o[mf][nt][3]);
            }
    }
    __syncthreads();
    if (h == 0) {
        #pragma unroll
        for (int mf = 0; mf < 2; mf++) {
            float i0 = 1.0f / ll[mf][0];
            float i1 = 1.0f / ll[mf][1];
            int ra = wr + 16 * mf + g;
            int rb = ra + 8;
            #pragma unroll
            for (int nt = 0; nt < 16; nt++) {
                int col = 8 * nt + 2 * tig;
                float2 a0 = *(float2*)(SQ  + ra * SQK + col);
                float2 b0 = *(float2*)(SKh + ra * SQK + col);
                float2 c0 = *(float2*)(SKl + ra * SQK + col);
                float2 a1 = *(float2*)(SQ  + rb * SQK + col);
                float2 b1 = *(float2*)(SKh + rb * SQK + col);
                float2 c1 = *(float2*)(SKl + rb * SQK + col);
                *(float2*)(out + (size_t)(qrow0 + ra) * DIM + col) =
                    make_float2((o[mf][nt][0] + a0.x + b0.x + c0.x) * i0,
                                (o[mf][nt][1] + a0.y + b0.y + c0.y) * i0);
                *(float2*)(out + (size_t)(qrow0 + rb) * DIM + col) =
                    make_float2((o[mf][nt][2] + a1.x + b1.x + c1.x) * i1,
                                (o[mf][nt][3] + a1.y + b1.y + c1.y) * i1);
            }
        }
    }
}

extern "C" void kernel_launch(void* const* d_in, const int* in_sizes, int n_in,
                              void* d_out, int out_size) {
    const float* q = (const float*)d_in[0];
    const float* k = (const float*)d_in[1];
    const float* v = (const float*)d_in[2];
    float* out = (float*)d_out;

    const int smem_bytes = SMEM_FLOATS * (int)sizeof(float);  // 190,464 B
    cudaFuncSetAttribute(fa_tf32_kernel,
                         cudaFuncAttributeMaxDynamicSharedMemorySize, smem_bytes);

    dim3 grid(NSEQ / BM);   // 128 CTAs
    dim3 block(256);
    fa_tf32_kernel<<<grid, block, smem_bytes>>>(q, k, v, out);
}

// round 10
// speedup vs baseline: 1.0103x; 1.0100x over previous
#include <cuda_runtime.h>
#include <cstdint>

// FlashAttention via 3xTF32 mma.sync, 16 warps = 4 row-groups x 4 key-quarters.
// 512 threads -> 4 warps/SMSP for latency hiding (R4 had 2).
// Warp tile: M=16 rows, N=16 keys. P is warp-private.
// N=8192, D=128, no softmax scaling. sm_103a (legacy tensor path; tcgen05
// unavailable: harness PTX targets sm_103 without the 'a' feature set).

#define NSEQ 8192
#define DIM 128
#define BM 64
#define BN 64
#define SQK 132   // 132 % 32 == 4 -> (4g+tig) banks conflict-free
#define SVS 136   // 136 % 32 == 8 -> (8tig+g) banks conflict-free
#define SPS 68    //  68 % 32 == 4

// SQ + SKh + SKl (64x132) + SVh + SVl (64x136) + SP (64x68) + stats
#define SMEM_FLOATS (3*BM*SQK + 2*BN*SVS + BM*SPS + 512)

__device__ __forceinline__ uint32_t f2tf(float x) {
    uint32_t r;
    asm("cvt.rna.tf32.f32 %0, %1;" : "=r"(r) : "f"(x));
    return r;
}
__device__ __forceinline__ void tf_split(float x, uint32_t& hi, uint32_t& lo) {
    hi = f2tf(x);
    lo = f2tf(x - __uint_as_float(hi));
}
__device__ __forceinline__ void split1(float x, float& h, float& l) {
    h = __uint_as_float(f2tf(x));
    l = __uint_as_float(f2tf(x - h));
}
__device__ __forceinline__ void mma_tf32(float* c, const uint32_t* a,
                                         uint32_t b0, uint32_t b1) {
    asm volatile(
        "mma.sync.aligned.m16n8k8.row.col.f32.tf32.tf32.f32 "
        "{%0,%1,%2,%3}, {%4,%5,%6,%7}, {%8,%9}, {%0,%1,%2,%3};"
        : "+f"(c[0]), "+f"(c[1]), "+f"(c[2]), "+f"(c[3])
        : "r"(a[0]), "r"(a[1]), "r"(a[2]), "r"(a[3]), "r"(b0), "r"(b1));
}

__global__ __launch_bounds__(512, 1)
void fa_tf32_kernel(const float* __restrict__ q,
                    const float* __restrict__ k,
                    const float* __restrict__ v,
                    float* __restrict__ out) {
    extern __shared__ float sm[];
    float* SQ  = sm;                      // 64 x 132 fp32
    float* SKh = SQ  + BM * SQK;          // 64 x 132 tf32-hi
    float* SKl = SKh + BN * SQK;          // 64 x 132 tf32-lo
    float* SVh = SKl + BN * SQK;          // 64 x 136
    float* SVl = SVh + BN * SVS;          // 64 x 136
    float* SP  = SVl + BN * SVS;          // 64 x 68 fp32 (warp-private quarters)
    float* SMx = SP  + BM * SPS;          // 4 x 64
    float* SSm = SMx + 256;               // 4 x 64

    const int tid  = threadIdx.x;
    const int warp = tid >> 5;
    const int lane = tid & 31;
    const int g    = lane >> 2;
    const int tig  = lane & 3;
    const int rg   = warp & 3;     // row group: rows rg*16 .. +15
    const int h    = warp >> 2;    // key/j quarter: keys h*16 .. +15
    const int wr   = rg * 16;
    const int qrow0 = blockIdx.x * BM;

    // ---- load Q tile fp32 ----
    {
        const float4* qg = (const float4*)(q + (size_t)qrow0 * DIM);
        #pragma unroll
        for (int t = 0; t < 4; t++) {
            int i = tid + 512 * t;       // 2048 float4
            int row = i >> 5;
            int dd = (i & 31) << 2;
            *(float4*)(SQ + row * SQK + dd) = qg[i];
        }
    }

    float o[16][4];
    #pragma unroll
    for (int nt = 0; nt < 16; nt++)
        #pragma unroll
        for (int i = 0; i < 4; i++) o[nt][i] = 0.0f;
    float m0 = -1e30f, m1 = -1e30f, l0 = 0.0f, l1 = 0.0f;

    const float* Sq0 = SQ + (wr + g) * SQK;       // row wr+g
    const float* Sq1 = Sq0 + 8 * SQK;             // row wr+8+g
    float* Sp0 = SP + (wr + g) * SPS;
    float* Sp1 = Sp0 + 8 * SPS;

    #pragma unroll 1
    for (int kb = 0; kb < NSEQ / BN; kb++) {
        __syncthreads();   // prior iter's SK/SV reads complete

        // ---- stream K,V; split hi/lo in registers ----
        {
            const float4* kg = (const float4*)(k + (size_t)kb * BN * DIM);
            const float4* vg = (const float4*)(v + (size_t)kb * BN * DIM);
            #pragma unroll
            for (int t = 0; t < 4; t++) {
                int i = tid + 512 * t;
                int row = i >> 5;
                int dd = (i & 31) << 2;
                float4 kx = kg[i], vx = vg[i];
                float4 xh, xl;
                split1(kx.x, xh.x, xl.x); split1(kx.y, xh.y, xl.y);
                split1(kx.z, xh.z, xl.z); split1(kx.w, xh.w, xl.w);
                *(float4*)(SKh + row * SQK + dd) = xh;
                *(float4*)(SKl + row * SQK + dd) = xl;
                split1(vx.x, xh.x, xl.x); split1(vx.y, xh.y, xl.y);
                split1(vx.z, xh.z, xl.z); split1(vx.w, xh.w, xl.w);
                *(float4*)(SVh + row * SVS + dd) = xh;
                *(float4*)(SVl + row * SVS + dd) = xl;
            }
        }
        __syncthreads();

        // ---- S = Q K^T : 1 m-frag x 2 n-tiles (this warp's 16 keys) ----
        float s[2][4];
        #pragma unroll
        for (int nt = 0; nt < 2; nt++)
            #pragma unroll
            for (int i = 0; i < 4; i++) s[nt][i] = 0.0f;

        #pragma unroll 4
        for (int kc = 0; kc < DIM / 8; kc++) {
            uint32_t ah[4], al[4];
            tf_split(Sq0[8 * kc + tig],     ah[0], al[0]);
            tf_split(Sq1[8 * kc + tig],     ah[1], al[1]);
            tf_split(Sq0[8 * kc + tig + 4], ah[2], al[2]);
            tf_split(Sq1[8 * kc + tig + 4], ah[3], al[3]);
            #pragma unroll
            for (int nt = 0; nt < 2; nt++) {
                int ntg = h * 2 + nt;
                const float* kph = SKh + (ntg * 8 + g) * SQK + 8 * kc + tig;
                const float* kpl = SKl + (ntg * 8 + g) * SQK + 8 * kc + tig;
                uint32_t bh0 = __float_as_uint(kph[0]);
                uint32_t bh1 = __float_as_uint(kph[4]);
                uint32_t bl0 = __float_as_uint(kpl[0]);
                uint32_t bl1 = __float_as_uint(kpl[4]);
                mma_tf32(s[nt], ah, bh0, bh1);
                mma_tf32(s[nt], ah, bl0, bl1);
                mma_tf32(s[nt], al, bh0, bh1);
            }
        }

        // ---- softmax: local row max, 4-way cross-quarter exchange ----
        float mx0 = fmaxf(fmaxf(s[0][0], s[0][1]), fmaxf(s[1][0], s[1][1]));
        float mx1 = fmaxf(fmaxf(s[0][2], s[0][3]), fmaxf(s[1][2], s[1][3]));
        #pragma unroll
        for (int w = 1; w < 4; w <<= 1) {
            mx0 = fmaxf(mx0, __shfl_xor_sync(0xffffffffu, mx0, w));
            mx1 = fmaxf(mx1, __shfl_xor_sync(0xffffffffu, mx1, w));
        }
        if (tig == 0) {
            SMx[h * 64 + wr + g]     = mx0;
            SMx[h * 64 + wr + 8 + g] = mx1;
        }
        __syncthreads();
        {
            int r0 = wr + g, r1 = wr + 8 + g;
            mx0 = fmaxf(fmaxf(SMx[r0], SMx[64 + r0]),
                        fmaxf(SMx[128 + r0], SMx[192 + r0]));
            mx1 = fmaxf(fmaxf(SMx[r1], SMx[64 + r1]),
                        fmaxf(SMx[128 + r1], SMx[192 + r1]));
        }
        float mn0 = fmaxf(m0, mx0), mn1 = fmaxf(m1, mx1);
        float alpha0 = __expf(m0 - mn0), alpha1 = __expf(m1 - mn1);
        m0 = mn0; m1 = mn1;

        float sum0 = 0.0f, sum1 = 0.0f;
        #pragma unroll
        for (int nt = 0; nt < 2; nt++) {
            s[nt][0] = __expf(s[nt][0] - mn0);
            s[nt][1] = __expf(s[nt][1] - mn0);
            s[nt][2] = __expf(s[nt][2] - mn1);
            s[nt][3] = __expf(s[nt][3] - mn1);
            sum0 += s[nt][0] + s[nt][1];
            sum1 += s[nt][2] + s[nt][3];
        }
        #pragma unroll
        for (int w = 1; w < 4; w <<= 1) {
            sum0 += __shfl_xor_sync(0xffffffffu, sum0, w);
            sum1 += __shfl_xor_sync(0xffffffffu, sum1, w);
        }
        if (tig == 0) {
            SSm[h * 64 + wr + g]     = sum0;
            SSm[h * 64 + wr + 8 + g] = sum1;
        }
        // write P (warp-private quarter)
        #pragma unroll
        for (int nt = 0; nt < 2; nt++) {
            int col = h * 16 + 8 * nt + 2 * tig;
            *(float2*)(Sp0 + col) = make_float2(s[nt][0], s[nt][1]);
            *(float2*)(Sp1 + col) = make_float2(s[nt][2], s[nt][3]);
        }
        __syncthreads();
        {
            int r0 = wr + g, r1 = wr + 8 + g;
            float t0 = (SSm[r0] + SSm[64 + r0]) + (SSm[128 + r0] + SSm[192 + r0]);
            float t1 = (SSm[r1] + SSm[64 + r1]) + (SSm[128 + r1] + SSm[192 + r1]);
            l0 = l0 * alpha0 + t0;
            l1 = l1 * alpha1 + t1;
        }

        // rescale O
        #pragma unroll
        for (int nt = 0; nt < 16; nt++) {
            o[nt][0] *= alpha0; o[nt][1] *= alpha0;
            o[nt][2] *= alpha1; o[nt][3] *= alpha1;
        }

        // ---- O += P V over this warp's j-quarter (16 j's = 2 k-chunks) ----
        #pragma unroll
        for (int kcl = 0; kcl < 2; kcl++) {
            int kcg = h * 2 + kcl;
            uint32_t pah[4], pal[4];
            tf_split(Sp0[8 * kcg + tig],     pah[0], pal[0]);
            tf_split(Sp1[8 * kcg + tig],     pah[1], pal[1]);
            tf_split(Sp0[8 * kcg + tig + 4], pah[2], pal[2]);
            tf_split(Sp1[8 * kcg + tig + 4], pah[3], pal[3]);
            #pragma unroll
            for (int nt = 0; nt < 16; nt++) {
                const float* vph = SVh + (8 * kcg + tig) * SVS + 8 * nt + g;
                const float* vpl = SVl + (8 * kcg + tig) * SVS + 8 * nt + g;
                uint32_t bh0 = __float_as_uint(vph[0]);
                uint32_t bh1 = __float_as_uint(vph[4 * SVS]);
                uint32_t bl0 = __float_as_uint(vpl[0]);
                uint32_t bl1 = __float_as_uint(vpl[4 * SVS]);
                mma_tf32(o[nt], pah, bh0, bh1);
                mma_tf32(o[nt], pah, bl0, bl1);
                mma_tf32(o[nt], pal, bh0, bh1);
            }
        }
    }

    // ---- epilogue: 4-way quarter combine via smem, normalize, store ----
    __syncthreads();
    if (h != 0) {
        float* OB = (h == 1) ? SQ : (h == 2) ? SKh : SKl;
        #pragma unroll
        for (int nt = 0; nt < 16; nt++) {
            int col = 8 * nt + 2 * tig;
            *(float2*)(OB + (wr + g) * SQK + col) = make_float2(o[nt][0], o[nt][1]);
            *(float2*)(OB + (wr + 8 + g) * SQK + col) = make_float2(o[nt][2], o[nt][3]);
        }
    }
    __syncthreads();
    if (h == 0) {
        float i0 = 1.0f / l0;
        float i1 = 1.0f / l1;
        int ra = wr + g;
        int rb = ra + 8;
        #pragma unroll
        for (int nt = 0; nt < 16; nt++) {
            int col = 8 * nt + 2 * tig;
            float2 a0 = *(float2*)(SQ  + ra * SQK + col);
            float2 b0 = *(float2*)(SKh + ra * SQK + col);
            float2 c0 = *(float2*)(SKl + ra * SQK + col);
            float2 a1 = *(float2*)(SQ  + rb * SQK + col);
            float2 b1 = *(float2*)(SKh + rb * SQK + col);
            float2 c1 = *(float2*)(SKl + rb * SQK + col);
            *(float2*)(out + (size_t)(qrow0 + ra) * DIM + col) =
                make_float2((o[nt][0] + a0.x + b0.x + c0.x) * i0,
                            (o[nt][1] + a0.y + b0.y + c0.y) * i0);
            *(float2*)(out + (size_t)(qrow0 + rb) * DIM + col) =
                make_float2((o[nt][2] + a1.x + b1.x + c1.x) * i1,
                            (o[nt][3] + a1.y + b1.y + c1.y) * i1);
        }
    }
}

extern "C" void kernel_launch(void* const* d_in, const int* in_sizes, int n_in,
                              void* d_out, int out_size) {
    const float* q = (const float*)d_in[0];
    const float* k = (const float*)d_in[1];
    const float* v = (const float*)d_in[2];
    float* out = (float*)d_out;

    const int smem_bytes = SMEM_FLOATS * (int)sizeof(float);  // 190,464 B
    cudaFuncSetAttribute(fa_tf32_kernel,
                         cudaFuncAttributeMaxDynamicSharedMemorySize, smem_bytes);

    dim3 grid(NSEQ / BM);   // 128 CTAs
    dim3 block(512);
    fa_tf32_kernel<<<grid, block, smem_bytes>>>(q, k, v, out);
}

// round 11
// speedup vs baseline: 1.7010x; 1.6836x over previous
#include <cuda_runtime.h>
#include <cstdint>

// FlashAttention via 3-pass bf16 mma.sync m16n8k16 (x = b0+b1, products
// b0c0+b0c1+b1c0; score noise ~5e-5 -> rel_err ~1e-4 << 1e-3).
// 16 warps = 4 row-groups x 4 key-quarters, BM=64, BN=64, grid 128.
// K and V pre-split/packed to bf16 pair-words in GMEM by prep kernels:
//   g_kp[j][2*dp+w]  : (b_w(d=2dp), b_w(2dp+1)) packed along d  (QK B-frags)
//   g_vp[jp][2*d+w]  : (b_w(j=2jp,d), b_w(2jp+1,d)) packed along j (PV B-frags)
// Q packed the same way as K into smem at prologue. P stays in registers:
// QK C-frag cols == PV A-frag k mapping, so A-frags are packed in place.

#define NSEQ 8192
#define DIM 128
#define BM 64
#define BN 64

// smem word (u32) offsets: Q 64x136, K 64x136, V(jp) 32x264, stats
#define QW 0
#define KW 8704
#define VW 17408
#define MXW 25856
#define SMW 26112
#define SMEM_WORDS 26368          // 105,472 B

__device__ uint32_t g_kp[NSEQ * DIM];        // 4 MB
__device__ uint32_t g_vp[(NSEQ / 2) * DIM * 2];  // 4 MB

__device__ __forceinline__ uint32_t pack2(float hi, float lo) {
    uint32_t r;
    asm("cvt.rn.bf16x2.f32 %0, %1, %2;" : "=r"(r) : "f"(hi), "f"(lo));
    return r;
}
__device__ __forceinline__ float up_lo(uint32_t w) { return __uint_as_float(w << 16); }
__device__ __forceinline__ float up_hi(uint32_t w) { return __uint_as_float(w & 0xffff0000u); }
// (lo,hi) floats -> b0 word + residual b1 word
__device__ __forceinline__ void split2(float lo, float hi, uint32_t& b0, uint32_t& b1) {
    b0 = pack2(hi, lo);
    b1 = pack2(hi - up_hi(b0), lo - up_lo(b0));
}
__device__ __forceinline__ void mma_bf16(float* c, const uint32_t* a,
                                         uint32_t b0, uint32_t b1) {
    asm volatile(
        "mma.sync.aligned.m16n8k16.row.col.f32.bf16.bf16.f32 "
        "{%0,%1,%2,%3}, {%4,%5,%6,%7}, {%8,%9}, {%0,%1,%2,%3};"
        : "+f"(c[0]), "+f"(c[1]), "+f"(c[2]), "+f"(c[3])
        : "r"(a[0]), "r"(a[1]), "r"(a[2]), "r"(a[3]), "r"(b0), "r"(b1));
}

// ---- prep K: float4 (4 d) -> word4 [b0(dp),b1(dp),b0(dp+1),b1(dp+1)] ----
__global__ __launch_bounds__(256)
void prep_k_kernel(const float* __restrict__ k) {
    int f = blockIdx.x * 256 + threadIdx.x;       // 8192*32 float4s
    float4 x = ((const float4*)k)[f];
    uint32_t w0, w1, w2, w3;
    split2(x.x, x.y, w0, w1);
    split2(x.z, x.w, w2, w3);
    ((uint4*)g_kp)[f] = make_uint4(w0, w1, w2, w3);
}

// ---- prep V: rows (2jp,2jp+1) same d-quad -> j-paired words ----
__global__ __launch_bounds__(256)
void prep_v_kernel(const float* __restrict__ v) {
    int p = blockIdx.x * 256 + threadIdx.x;       // 4096*32
    int jp = p >> 5, q4 = p & 31;
    float4 a = ((const float4*)v)[(2 * jp) * 32 + q4];      // row 2jp   (lo)
    float4 b = ((const float4*)v)[(2 * jp + 1) * 32 + q4];  // row 2jp+1 (hi)
    uint32_t w[8];
    split2(a.x, b.x, w[0], w[1]);
    split2(a.y, b.y, w[2], w[3]);
    split2(a.z, b.z, w[4], w[5]);
    split2(a.w, b.w, w[6], w[7]);
    uint4* o = (uint4*)g_vp;
    o[jp * 64 + 2 * q4]     = make_uint4(w[0], w[1], w[2], w[3]);
    o[jp * 64 + 2 * q4 + 1] = make_uint4(w[4], w[5], w[6], w[7]);
}

__global__ __launch_bounds__(512, 1)
void fa_bf16_kernel(const float* __restrict__ q, float* __restrict__ out) {
    extern __shared__ uint32_t smw[];
    float* smf = (float*)smw;
    float* SMx = smf + MXW;     // 4 x 64
    float* SSm = smf + SMW;     // 4 x 64

    const int tid  = threadIdx.x;
    const int warp = tid >> 5;
    const int lane = tid & 31;
    const int g    = lane >> 2;
    const int tig  = lane & 3;
    const int rg   = warp & 3;     // rows rg*16 .. +15
    const int h    = warp >> 2;    // keys/j h*16 .. +15
    const int wr   = rg * 16;
    const int qrow0 = blockIdx.x * BM;

    // ---- Q prologue: load, split2, pack into smem (same layout as K) ----
    {
        const float4* qg = (const float4*)(q + (size_t)qrow0 * DIM);
        #pragma unroll
        for (int t = 0; t < 4; t++) {
            int idx = tid + 512 * t;          // 2048 float4
            int row = idx >> 5, w4 = idx & 31;
            float4 x = qg[idx];
            uint32_t w0, w1, w2, w3;
            split2(x.x, x.y, w0, w1);
            split2(x.z, x.w, w2, w3);
            *(uint4*)(smw + QW + row * 136 + 4 * w4) = make_uint4(w0, w1, w2, w3);
        }
    }

    float o[16][4];
    #pragma unroll
    for (int nt = 0; nt < 16; nt++)
        #pragma unroll
        for (int i = 0; i < 4; i++) o[nt][i] = 0.0f;
    float m0 = -1e30f, m1 = -1e30f, l0 = 0.0f, l1 = 0.0f;

    const uint32_t* SQr0 = smw + QW + (wr + g) * 136;
    const uint32_t* SQr1 = SQr0 + 8 * 136;

    #pragma unroll 1
    for (int kb = 0; kb < NSEQ / BN; kb++) {
        __syncthreads();   // prior iter's smem reads complete (covers Q too)

        // ---- loader: pure copy of pre-packed K,V tiles ----
        {
            const uint4* kp = (const uint4*)g_kp + (size_t)kb * 2048;
            const uint4* vp = (const uint4*)g_vp + (size_t)kb * 2048;
            #pragma unroll
            for (int t = 0; t < 4; t++) {
                int idx = tid + 512 * t;
                int krow = idx >> 5, kw4 = idx & 31;
                *(uint4*)(smw + KW + krow * 136 + 4 * kw4) = kp[idx];
                int jp = idx >> 6, vw4 = idx & 63;
                *(uint4*)(smw + VW + jp * 264 + 4 * vw4) = vp[idx];
            }
        }
        __syncthreads();

        // ---- S = Q K^T : 8 k-chunks of 16, 2 n-tiles ----
        float s[2][4];
        #pragma unroll
        for (int nt = 0; nt < 2; nt++)
            #pragma unroll
            for (int i = 0; i < 4; i++) s[nt][i] = 0.0f;

        #pragma unroll
        for (int c = 0; c < 8; c++) {
            uint2 qa0 = *(const uint2*)(SQr0 + 2 * (8 * c + tig));
            uint2 qa1 = *(const uint2*)(SQr1 + 2 * (8 * c + tig));
            uint2 qa2 = *(const uint2*)(SQr0 + 2 * (8 * c + tig + 4));
            uint2 qa3 = *(const uint2*)(SQr1 + 2 * (8 * c + tig + 4));
            uint32_t A0[4] = {qa0.x, qa1.x, qa2.x, qa3.x};
            uint32_t A1[4] = {qa0.y, qa1.y, qa2.y, qa3.y};
            #pragma unroll
            for (int nt = 0; nt < 2; nt++) {
                const uint32_t* kr = smw + KW + (h * 16 + 8 * nt + g) * 136;
                uint2 kb0 = *(const uint2*)(kr + 2 * (8 * c + tig));
                uint2 kb1 = *(const uint2*)(kr + 2 * (8 * c + tig + 4));
                mma_bf16(s[nt], A0, kb0.x, kb1.x);   // q0*k0
                mma_bf16(s[nt], A0, kb0.y, kb1.y);   // q0*k1
                mma_bf16(s[nt], A1, kb0.x, kb1.x);   // q1*k0
            }
        }

        // ---- softmax: local row max, 4-way cross-quarter exchange ----
        float mx0 = fmaxf(fmaxf(s[0][0], s[0][1]), fmaxf(s[1][0], s[1][1]));
        float mx1 = fmaxf(fmaxf(s[0][2], s[0][3]), fmaxf(s[1][2], s[1][3]));
        #pragma unroll
        for (int w = 1; w < 4; w <<= 1) {
            mx0 = fmaxf(mx0, __shfl_xor_sync(0xffffffffu, mx0, w));
            mx1 = fmaxf(mx1, __shfl_xor_sync(0xffffffffu, mx1, w));
        }
        if (tig == 0) {
            SMx[h * 64 + wr + g]     = mx0;
            SMx[h * 64 + wr + 8 + g] = mx1;
        }
        __syncthreads();
        {
            int r0 = wr + g, r1 = wr + 8 + g;
            mx0 = fmaxf(fmaxf(SMx[r0], SMx[64 + r0]),
                        fmaxf(SMx[128 + r0], SMx[192 + r0]));
            mx1 = fmaxf(fmaxf(SMx[r1], SMx[64 + r1]),
                        fmaxf(SMx[128 + r1], SMx[192 + r1]));
        }
        float mn0 = fmaxf(m0, mx0), mn1 = fmaxf(m1, mx1);
        float alpha0 = __expf(m0 - mn0), alpha1 = __expf(m1 - mn1);
        m0 = mn0; m1 = mn1;

        float sum0 = 0.0f, sum1 = 0.0f;
        #pragma unroll
        for (int nt = 0; nt < 2; nt++) {
            s[nt][0] = __expf(s[nt][0] - mn0);
            s[nt][1] = __expf(s[nt][1] - mn0);
            s[nt][2] = __expf(s[nt][2] - mn1);
            s[nt][3] = __expf(s[nt][3] - mn1);
            sum0 += s[nt][0] + s[nt][1];
            sum1 += s[nt][2] + s[nt][3];
        }
        #pragma unroll
        for (int w = 1; w < 4; w <<= 1) {
            sum0 += __shfl_xor_sync(0xffffffffu, sum0, w);
            sum1 += __shfl_xor_sync(0xffffffffu, sum1, w);
        }
        if (tig == 0) {
            SSm[h * 64 + wr + g]     = sum0;
            SSm[h * 64 + wr + 8 + g] = sum1;
        }
        __syncthreads();
        {
            int r0 = wr + g, r1 = wr + 8 + g;
            float t0 = (SSm[r0] + SSm[64 + r0]) + (SSm[128 + r0] + SSm[192 + r0]);
            float t1 = (SSm[r1] + SSm[64 + r1]) + (SSm[128 + r1] + SSm[192 + r1]);
            l0 = l0 * alpha0 + t0;
            l1 = l1 * alpha1 + t1;
        }

        // rescale O
        #pragma unroll
        for (int nt = 0; nt < 16; nt++) {
            o[nt][0] *= alpha0; o[nt][1] *= alpha0;
            o[nt][2] *= alpha1; o[nt][3] *= alpha1;
        }

        // ---- O += P V : A-frags packed in-register from S c-frags ----
        {
            uint32_t P0[4], P1[4];
            P0[0] = pack2(s[0][1], s[0][0]);
            P0[1] = pack2(s[0][3], s[0][2]);
            P0[2] = pack2(s[1][1], s[1][0]);
            P0[3] = pack2(s[1][3], s[1][2]);
            P1[0] = pack2(s[0][1] - up_hi(P0[0]), s[0][0] - up_lo(P0[0]));
            P1[1] = pack2(s[0][3] - up_hi(P0[1]), s[0][2] - up_lo(P0[1]));
            P1[2] = pack2(s[1][1] - up_hi(P0[2]), s[1][0] - up_lo(P0[2]));
            P1[3] = pack2(s[1][3] - up_hi(P0[3]), s[1][2] - up_lo(P0[3]));

            const uint32_t* vr0 = smw + VW + (8 * h + tig) * 264;
            const uint32_t* vr1 = smw + VW + (8 * h + tig + 4) * 264;
            #pragma unroll
            for (int nt = 0; nt < 16; nt++) {
                uint2 v0 = *(const uint2*)(vr0 + 2 * (8 * nt + g));
                uint2 v1 = *(const uint2*)(vr1 + 2 * (8 * nt + g));
                mma_bf16(o[nt], P0, v0.x, v1.x);   // p0*v0
                mma_bf16(o[nt], P0, v0.y, v1.y);   // p0*v1
                mma_bf16(o[nt], P1, v0.x, v1.x);   // p1*v0
            }
        }
    }

    // ---- epilogue: 4-way quarter combine via smem, normalize, store ----
    __syncthreads();
    if (h != 0) {
        float* OB = (h == 1) ? smf : (h == 2) ? (smf + KW) : (smf + VW);
        #pragma unroll
        for (int nt = 0; nt < 16; nt++) {
            int col = 8 * nt + 2 * tig;
            *(float2*)(OB + (wr + g) * 132 + col) = make_float2(o[nt][0], o[nt][1]);
            *(float2*)(OB + (wr + 8 + g) * 132 + col) = make_float2(o[nt][2], o[nt][3]);
        }
    }
    __syncthreads();
    if (h == 0) {
        float i0 = 1.0f / l0;
        float i1 = 1.0f / l1;
        int ra = wr + g;
        int rb = ra + 8;
        #pragma unroll
        for (int nt = 0; nt < 16; nt++) {
            int col = 8 * nt + 2 * tig;
            float2 a0 = *(float2*)(smf + ra * 132 + col);
            float2 b0 = *(float2*)(smf + KW + ra * 132 + col);
            float2 c0 = *(float2*)(smf + VW + ra * 132 + col);
            float2 a1 = *(float2*)(smf + rb * 132 + col);
            float2 b1 = *(float2*)(smf + KW + rb * 132 + col);
            float2 c1 = *(float2*)(smf + VW + rb * 132 + col);
            *(float2*)(out + (size_t)(qrow0 + ra) * DIM + col) =
                make_float2((o[nt][0] + a0.x + b0.x + c0.x) * i0,
                            (o[nt][1] + a0.y + b0.y + c0.y) * i0);
            *(float2*)(out + (size_t)(qrow0 + rb) * DIM + col) =
                make_float2((o[nt][2] + a1.x + b1.x + c1.x) * i1,
                            (o[nt][3] + a1.y + b1.y + c1.y) * i1);
        }
    }
}

extern "C" void kernel_launch(void* const* d_in, const int* in_sizes, int n_in,
                              void* d_out, int out_size) {
    const float* q = (const float*)d_in[0];
    const float* k = (const float*)d_in[1];
    const float* v = (const float*)d_in[2];
    float* out = (float*)d_out;

    prep_k_kernel<<<NSEQ * 32 / 256, 256>>>(k);
    prep_v_kernel<<<NSEQ / 2 * 32 / 256, 256>>>(v);

    const int smem_bytes = SMEM_WORDS * 4;   // 105,472 B
    cudaFuncSetAttribute(fa_bf16_kernel,
                         cudaFuncAttributeMaxDynamicSharedMemorySize, smem_bytes);

    fa_bf16_kernel<<<NSEQ / BM, 512, smem_bytes>>>(q, out);
}